// round 12
// baseline (speedup 1.0000x reference)
#include <cuda_runtime.h>

// Density loss via exact KNN (k=16, self included) on [8, 2048, 3] clouds.
//
// Kernel A (16 blocks x 512): counting bucket-sort each cloud by x into 256
//   uniform buckets (minmax + histogram + scan + scatter).
// Kernel B (256 blocks x 128): each warp owns 32 consecutive bucketed points.
//   Seed top-16 from the 48 x-nearest candidates -> threshold t -> exact
//   conservative x-window via O(1) bucket lookup. Then a BRANCHLESS filter
//   scan: per candidate just distance + compare + unconditional local-mem
//   store + predicated counter (no sorting, no ballots in the hot loop).
//   Survivors (d < t, ~20-40 per lane) are sorted once at the end via the
//   Batcher merge network. Rare mid-scan flush bounds the buffer AND
//   tightens t. Reduction + MSE folded in with a last-block counter.

#define B 8
#define N 2048
#define KNN 16
#define CLOUDS 16
#define NB 256
#define SORT_THREADS 512
#define SCAN_THREADS 128          // 4 warps = 4 query groups of 32
#define CHUNKS 16                 // 128 queries per scan block
#define SCAN_BLOCKS (CLOUDS * CHUNKS)   // 256
#define CAP 64                    // per-lane survivor buffer (local mem)
#define FLUSH_AT (CAP - 16)

__device__ float4 g_sorted[CLOUDS * N];
__device__ int    g_bstart[CLOUDS][NB + 1];
__device__ float2 g_cinfo[CLOUDS];      // (xmin, scale)
__device__ float  g_partial[SCAN_BLOCKS];
__device__ int    g_count = 0;

#define CE(x, y) { float _lo = fminf((x), (y)); (y) = fmaxf((x), (y)); (x) = _lo; }

// Batcher sort of 16 candidates (63 CE), fold into sorted a (48 CE), t = a[15].
__device__ __forceinline__ void merge_batch(float (&a)[KNN], float (&c)[KNN], float& t) {
    CE(c[0], c[1]) CE(c[2], c[3]) CE(c[0], c[2]) CE(c[1], c[3]) CE(c[1], c[2])
    CE(c[4], c[5]) CE(c[6], c[7]) CE(c[4], c[6]) CE(c[5], c[7]) CE(c[5], c[6])
    CE(c[0], c[4]) CE(c[2], c[6]) CE(c[2], c[4])
    CE(c[1], c[5]) CE(c[3], c[7]) CE(c[3], c[5])
    CE(c[1], c[2]) CE(c[3], c[4]) CE(c[5], c[6])
    CE(c[8], c[9]) CE(c[10], c[11]) CE(c[8], c[10]) CE(c[9], c[11]) CE(c[9], c[10])
    CE(c[12], c[13]) CE(c[14], c[15]) CE(c[12], c[14]) CE(c[13], c[15]) CE(c[13], c[14])
    CE(c[8], c[12]) CE(c[10], c[14]) CE(c[10], c[12])
    CE(c[9], c[13]) CE(c[11], c[15]) CE(c[11], c[13])
    CE(c[9], c[10]) CE(c[11], c[12]) CE(c[13], c[14])
    CE(c[0], c[8])  CE(c[4], c[12]) CE(c[4], c[8])
    CE(c[2], c[10]) CE(c[6], c[14]) CE(c[6], c[10])
    CE(c[2], c[4])  CE(c[6], c[8])  CE(c[10], c[12])
    CE(c[1], c[9])  CE(c[5], c[13]) CE(c[5], c[9])
    CE(c[3], c[11]) CE(c[7], c[15]) CE(c[7], c[11])
    CE(c[3], c[5])  CE(c[7], c[9])  CE(c[11], c[13])
    CE(c[1], c[2]) CE(c[3], c[4]) CE(c[5], c[6]) CE(c[7], c[8])
    CE(c[9], c[10]) CE(c[11], c[12]) CE(c[13], c[14])

#pragma unroll
    for (int q = 0; q < KNN; ++q) a[q] = fminf(a[q], c[15 - q]);
#pragma unroll
    for (int q = 0; q < 8; ++q) CE(a[q], a[q + 8])
    CE(a[0], a[4]) CE(a[1], a[5]) CE(a[2], a[6]) CE(a[3], a[7])
    CE(a[8], a[12]) CE(a[9], a[13]) CE(a[10], a[14]) CE(a[11], a[15])
    CE(a[0], a[2]) CE(a[1], a[3]) CE(a[4], a[6]) CE(a[5], a[7])
    CE(a[8], a[10]) CE(a[9], a[11]) CE(a[12], a[14]) CE(a[13], a[15])
    CE(a[0], a[1]) CE(a[2], a[3]) CE(a[4], a[5]) CE(a[6], a[7])
    CE(a[8], a[9]) CE(a[10], a[11]) CE(a[12], a[13]) CE(a[14], a[15])

    t = a[15];
}

__device__ __forceinline__ void flush_buf(float* buf, int& cnt,
                                          float (&a)[KNN], float& t) {
    int processed = 0;
    while (processed < cnt) {
        float c[16];
#pragma unroll
        for (int q = 0; q < 16; ++q) {
            int idx = processed + q;
            c[q] = (idx < cnt) ? buf[idx] : 3.4e38f;
        }
        merge_batch(a, c, t);
        processed += 16;
    }
    cnt = 0;
}

// ---------------- Kernel A: counting bucket-sort per cloud ----------------
__global__ __launch_bounds__(SORT_THREADS)
void bucket_kernel(const float* __restrict__ seed, const float* __restrict__ gt_s) {
    __shared__ float rmin[SORT_THREADS], rmax[SORT_THREADS];
    __shared__ int hist[NB];
    __shared__ int cursor[NB];

    const int cloud = blockIdx.x;
    const int tid   = threadIdx.x;
    const float* __restrict__ src =
        ((cloud >> 3) == 0 ? seed : gt_s) + (size_t)(cloud & 7) * N * 3;

    float lmin = 3.4e38f, lmax = -3.4e38f;
    for (int i = tid; i < N; i += SORT_THREADS) {
        float x = src[3 * i];
        lmin = fminf(lmin, x);
        lmax = fmaxf(lmax, x);
    }
    rmin[tid] = lmin; rmax[tid] = lmax;
    __syncthreads();
    for (int s = SORT_THREADS / 2; s > 0; s >>= 1) {
        if (tid < s) {
            rmin[tid] = fminf(rmin[tid], rmin[tid + s]);
            rmax[tid] = fmaxf(rmax[tid], rmax[tid + s]);
        }
        __syncthreads();
    }
    const float xmin  = rmin[0];
    const float range = rmax[0] - xmin;
    const float scale = (float)NB / fmaxf(range * (1.0f + 1e-6f), 1e-30f);

    if (tid < NB) hist[tid] = 0;
    __syncthreads();
    for (int i = tid; i < N; i += SORT_THREADS) {
        int b = (int)((src[3 * i] - xmin) * scale);
        b = max(0, min(NB - 1, b));
        atomicAdd(&hist[b], 1);
    }
    __syncthreads();

    // inclusive scan over NB entries (all threads hit the barriers)
    int val = (tid < NB) ? hist[tid] : 0;
    for (int off = 1; off < NB; off <<= 1) {
        int u = (tid >= off && tid < NB) ? hist[tid - off] : 0;
        __syncthreads();
        if (tid < NB) { val += u; hist[tid] = val; }
        __syncthreads();
    }
    if (tid < NB) {
        int start = (tid == 0) ? 0 : hist[tid - 1];
        g_bstart[cloud][tid] = start;
        cursor[tid] = start;
    }
    if (tid == 0) g_bstart[cloud][NB] = N;
    __syncthreads();

    float4* __restrict__ dst = g_sorted + (size_t)cloud * N;
    for (int i = tid; i < N; i += SORT_THREADS) {
        float x = src[3 * i], y = src[3 * i + 1], z = src[3 * i + 2];
        int b = (int)((x - xmin) * scale);
        b = max(0, min(NB - 1, b));
        int pos = atomicAdd(&cursor[b], 1);
        dst[pos] = make_float4(x, y, z, x * x + y * y + z * z);
    }
    if (tid == 0) g_cinfo[cloud] = make_float2(xmin, scale);
}

// ---------------- Kernel B: filter-then-sort exact top-16 ----------------
__global__ __launch_bounds__(SCAN_THREADS)
void scan_kernel(float* __restrict__ out) {
    __shared__ float4 spts[N];               // 32 KB (bucketed by x)
    __shared__ int sbstart[NB + 1];
    __shared__ float red[SCAN_THREADS];
    __shared__ float dd[CLOUDS];
    __shared__ int last;

    const int bx    = blockIdx.x;
    const int cloud = bx >> 4;
    const int chunk = bx & 15;
    const int tid   = threadIdx.x;
    const int wid   = tid >> 5;
    const int lane  = tid & 31;

    const float4* __restrict__ gs = g_sorted + (size_t)cloud * N;
    for (int i = tid; i < N; i += SCAN_THREADS) spts[i] = gs[i];
    for (int i = tid; i < NB + 1; i += SCAN_THREADS) sbstart[i] = g_bstart[cloud][i];
    const float2 ci = g_cinfo[cloud];
    __syncthreads();

    const int qbase = chunk * SCAN_THREADS + wid * 32;
    const int myp   = qbase + lane;

    const float4 xi = spts[myp];
    const float ai = xi.w;
    const float mx = -2.0f * xi.x;
    const float my = -2.0f * xi.y;
    const float mz = -2.0f * xi.z;

    float a[KNN];
#pragma unroll
    for (int q = 0; q < KNN; ++q) a[q] = 3.4e38f;
    float t = 3.4e38f;

    // ---- seed: 3 batches (48 x-nearest candidates incl. self) ----
    int s0 = qbase - 16;
    if (s0 < 0) s0 = 0;
    if (s0 > N - 48) s0 = N - 48;
#pragma unroll
    for (int s = 0; s < 3; ++s) {
        float c[16];
#pragma unroll
        for (int q = 0; q < 16; ++q) {
            float4 sp = spts[s0 + 16 * s + q];
            float d = ai + sp.w;
            d = fmaf(mx, sp.x, d);
            d = fmaf(my, sp.y, d);
            d = fmaf(mz, sp.z, d);
            c[q] = d;
        }
        merge_batch(a, c, t);
    }

    // ---- exact conservative window from seeded t (warp-uniform) ----
    float r = sqrtf(t) * 1.0000002f;
    float xlo = xi.x - r;
    float xhi = xi.x + r;
#pragma unroll
    for (int off = 16; off >= 1; off >>= 1) {
        xlo = fminf(xlo, __shfl_xor_sync(0xffffffffu, xlo, off));
        xhi = fmaxf(xhi, __shfl_xor_sync(0xffffffffu, xhi, off));
    }
    int b_lo = (int)((xlo - ci.x) * ci.y); b_lo = max(0, min(NB - 1, b_lo));
    int b_hi = (int)((xhi - ci.x) * ci.y); b_hi = max(0, min(NB - 1, b_hi));
    const int w_lo = sbstart[b_lo];
    const int w_hi = sbstart[b_hi + 1];

    // ---- branchless filter scan (skipping the 48 seed candidates) ----
    float buf[CAP];                 // local memory, per-lane survivor stack
    int cnt = 0;

    auto scan_range = [&](int beg, int end) {
        for (int j = beg; j < end; ) {
            int stop = min(end, j + 16);
#pragma unroll 4
            for (; j < stop; ++j) {
                float4 sp = spts[j];           // warp-broadcast LDS.128
                float d = ai + sp.w;
                d = fmaf(mx, sp.x, d);
                d = fmaf(my, sp.y, d);
                d = fmaf(mz, sp.z, d);
                buf[cnt] = d;                  // unconditional store (slack ok)
                cnt += (d < t) ? 1 : 0;        // predicated bump
            }
            if (cnt >= FLUSH_AT) flush_buf(buf, cnt, a, t);  // rare; tightens t
        }
    };

    scan_range(w_lo, min(w_hi, s0));
    scan_range(max(w_lo, s0 + 48), w_hi);
    flush_buf(buf, cnt, a, t);

    // ---- per-point mean of 16 nearest ----
    float s16 = 0.0f;
#pragma unroll
    for (int q = 0; q < KNN; ++q) s16 += a[q];
    red[tid] = s16 * (1.0f / KNN);
    __syncthreads();

    // ---- block reduction ----
#pragma unroll
    for (int s = SCAN_THREADS / 2; s > 0; s >>= 1) {
        if (tid < s) red[tid] += red[tid + s];
        __syncthreads();
    }
    if (tid == 0) g_partial[bx] = red[0];

    // ---- last-block finalize ----
    __threadfence();
    if (tid == 0) last = (atomicAdd(&g_count, 1) == SCAN_BLOCKS - 1);
    __syncthreads();
    if (last) {
        if (tid < CLOUDS) {
            float s = 0.0f;
#pragma unroll
            for (int c2 = 0; c2 < CHUNKS; ++c2)
                s += __ldcg(&g_partial[tid * CHUNKS + c2]);
            dd[tid] = s * (1.0f / N);
        }
        __syncthreads();
        if (tid == 0) {
            float loss = 0.0f;
#pragma unroll
            for (int b = 0; b < B; ++b) {
                float df = dd[b] - dd[B + b];
                loss += df * df;
            }
            out[0] = loss * (1.0f / B);
            g_count = 0;   // reset for next graph replay
        }
    }
}

extern "C" void kernel_launch(void* const* d_in, const int* in_sizes, int n_in,
                              void* d_out, int out_size) {
    const float* seed = (const float*)d_in[0];
    const float* gt_s = (const float*)d_in[1];
    float* out = (float*)d_out;

    bucket_kernel<<<CLOUDS, SORT_THREADS>>>(seed, gt_s);
    scan_kernel<<<SCAN_BLOCKS, SCAN_THREADS>>>(out);
}

// round 13
// speedup vs baseline: 2.6715x; 2.6715x over previous
#include <cuda_runtime.h>

// Density loss via exact KNN (k=16, self included) on [8, 2048, 3] clouds.
//
// Kernel A (16 blocks x 512): counting bucket-sort each cloud by x into 256
//   uniform buckets (minmax + histogram + scan + scatter).
// Kernel B (256 blocks x 128): each warp owns 32 consecutive bucketed points.
//   Seed top-16 from the 48 x-nearest candidates -> threshold t -> exact
//   conservative x-window via O(1) bucket lookup. Branchless filter scan:
//   per candidate = distance + compare + unconditional SMEM store (lane-major
//   per-lane stack, conflict-free) + predicated count. Survivors are sorted
//   once via the Batcher merge network (rare warp-uniform flushes tighten t).
//   Reduction + MSE folded in with a last-block counter.

#define B 8
#define N 2048
#define KNN 16
#define CLOUDS 16
#define NB 256
#define SORT_THREADS 512
#define SCAN_THREADS 128          // 4 warps = 4 query groups of 32
#define WARPS (SCAN_THREADS / 32)
#define CHUNKS 16                 // 128 queries per scan block
#define SCAN_BLOCKS (CLOUDS * CHUNKS)   // 256
#define CAP 48                    // per-lane survivor stack depth (smem)
#define FLUSH_AT (CAP - 16)

#define SMEM_PTS_BYTES   (N * 16)                       // 32 KB
#define SMEM_STK_BYTES   (WARPS * CAP * 32 * 4)         // 24 KB
#define SMEM_DYN_BYTES   (SMEM_PTS_BYTES + SMEM_STK_BYTES)

__device__ float4 g_sorted[CLOUDS * N];
__device__ int    g_bstart[CLOUDS][NB + 1];
__device__ float2 g_cinfo[CLOUDS];      // (xmin, scale)
__device__ float  g_partial[SCAN_BLOCKS];
__device__ int    g_count = 0;

#define CE(x, y) { float _lo = fminf((x), (y)); (y) = fmaxf((x), (y)); (x) = _lo; }

// Batcher sort of 16 candidates (63 CE), fold into sorted a (48 CE), t = a[15].
__device__ __forceinline__ void merge_batch(float (&a)[KNN], float (&c)[KNN], float& t) {
    CE(c[0], c[1]) CE(c[2], c[3]) CE(c[0], c[2]) CE(c[1], c[3]) CE(c[1], c[2])
    CE(c[4], c[5]) CE(c[6], c[7]) CE(c[4], c[6]) CE(c[5], c[7]) CE(c[5], c[6])
    CE(c[0], c[4]) CE(c[2], c[6]) CE(c[2], c[4])
    CE(c[1], c[5]) CE(c[3], c[7]) CE(c[3], c[5])
    CE(c[1], c[2]) CE(c[3], c[4]) CE(c[5], c[6])
    CE(c[8], c[9]) CE(c[10], c[11]) CE(c[8], c[10]) CE(c[9], c[11]) CE(c[9], c[10])
    CE(c[12], c[13]) CE(c[14], c[15]) CE(c[12], c[14]) CE(c[13], c[15]) CE(c[13], c[14])
    CE(c[8], c[12]) CE(c[10], c[14]) CE(c[10], c[12])
    CE(c[9], c[13]) CE(c[11], c[15]) CE(c[11], c[13])
    CE(c[9], c[10]) CE(c[11], c[12]) CE(c[13], c[14])
    CE(c[0], c[8])  CE(c[4], c[12]) CE(c[4], c[8])
    CE(c[2], c[10]) CE(c[6], c[14]) CE(c[6], c[10])
    CE(c[2], c[4])  CE(c[6], c[8])  CE(c[10], c[12])
    CE(c[1], c[9])  CE(c[5], c[13]) CE(c[5], c[9])
    CE(c[3], c[11]) CE(c[7], c[15]) CE(c[7], c[11])
    CE(c[3], c[5])  CE(c[7], c[9])  CE(c[11], c[13])
    CE(c[1], c[2]) CE(c[3], c[4]) CE(c[5], c[6]) CE(c[7], c[8])
    CE(c[9], c[10]) CE(c[11], c[12]) CE(c[13], c[14])

#pragma unroll
    for (int q = 0; q < KNN; ++q) a[q] = fminf(a[q], c[15 - q]);
#pragma unroll
    for (int q = 0; q < 8; ++q) CE(a[q], a[q + 8])
    CE(a[0], a[4]) CE(a[1], a[5]) CE(a[2], a[6]) CE(a[3], a[7])
    CE(a[8], a[12]) CE(a[9], a[13]) CE(a[10], a[14]) CE(a[11], a[15])
    CE(a[0], a[2]) CE(a[1], a[3]) CE(a[4], a[6]) CE(a[5], a[7])
    CE(a[8], a[10]) CE(a[9], a[11]) CE(a[12], a[14]) CE(a[13], a[15])
    CE(a[0], a[1]) CE(a[2], a[3]) CE(a[4], a[5]) CE(a[6], a[7])
    CE(a[8], a[9]) CE(a[10], a[11]) CE(a[12], a[13]) CE(a[14], a[15])

    t = a[15];
}

// Warp-uniform flush of per-lane smem stacks into sorted top-16 lists.
__device__ __forceinline__ void flush_stk(float* __restrict__ stk, int lane,
                                          int& cnt, float (&a)[KNN], float& t) {
    unsigned mx = __reduce_max_sync(0xffffffffu, (unsigned)cnt);
    for (int p = 0; p < (int)mx; p += 16) {
        float c[16];
#pragma unroll
        for (int q = 0; q < 16; ++q) {
            int idx = p + q;
            c[q] = (idx < cnt) ? stk[idx * 32 + lane] : 3.4e38f;
        }
        merge_batch(a, c, t);
    }
    cnt = 0;
}

// ---------------- Kernel A: counting bucket-sort per cloud ----------------
__global__ __launch_bounds__(SORT_THREADS)
void bucket_kernel(const float* __restrict__ seed, const float* __restrict__ gt_s) {
    __shared__ float rmin[SORT_THREADS], rmax[SORT_THREADS];
    __shared__ int hist[NB];
    __shared__ int cursor[NB];

    const int cloud = blockIdx.x;
    const int tid   = threadIdx.x;
    const float* __restrict__ src =
        ((cloud >> 3) == 0 ? seed : gt_s) + (size_t)(cloud & 7) * N * 3;

    float lmin = 3.4e38f, lmax = -3.4e38f;
    for (int i = tid; i < N; i += SORT_THREADS) {
        float x = src[3 * i];
        lmin = fminf(lmin, x);
        lmax = fmaxf(lmax, x);
    }
    rmin[tid] = lmin; rmax[tid] = lmax;
    __syncthreads();
    for (int s = SORT_THREADS / 2; s > 0; s >>= 1) {
        if (tid < s) {
            rmin[tid] = fminf(rmin[tid], rmin[tid + s]);
            rmax[tid] = fmaxf(rmax[tid], rmax[tid + s]);
        }
        __syncthreads();
    }
    const float xmin  = rmin[0];
    const float range = rmax[0] - xmin;
    const float scale = (float)NB / fmaxf(range * (1.0f + 1e-6f), 1e-30f);

    if (tid < NB) hist[tid] = 0;
    __syncthreads();
    for (int i = tid; i < N; i += SORT_THREADS) {
        int b = (int)((src[3 * i] - xmin) * scale);
        b = max(0, min(NB - 1, b));
        atomicAdd(&hist[b], 1);
    }
    __syncthreads();

    int val = (tid < NB) ? hist[tid] : 0;
    for (int off = 1; off < NB; off <<= 1) {
        int u = (tid >= off && tid < NB) ? hist[tid - off] : 0;
        __syncthreads();
        if (tid < NB) { val += u; hist[tid] = val; }
        __syncthreads();
    }
    if (tid < NB) {
        int start = (tid == 0) ? 0 : hist[tid - 1];
        g_bstart[cloud][tid] = start;
        cursor[tid] = start;
    }
    if (tid == 0) g_bstart[cloud][NB] = N;
    __syncthreads();

    float4* __restrict__ dst = g_sorted + (size_t)cloud * N;
    for (int i = tid; i < N; i += SORT_THREADS) {
        float x = src[3 * i], y = src[3 * i + 1], z = src[3 * i + 2];
        int b = (int)((x - xmin) * scale);
        b = max(0, min(NB - 1, b));
        int pos = atomicAdd(&cursor[b], 1);
        dst[pos] = make_float4(x, y, z, x * x + y * y + z * z);
    }
    if (tid == 0) g_cinfo[cloud] = make_float2(xmin, scale);
}

// ---------------- Kernel B: filter-then-sort exact top-16 ----------------
__global__ __launch_bounds__(SCAN_THREADS)
void scan_kernel(float* __restrict__ out) {
    extern __shared__ char dyn[];
    float4* spts = reinterpret_cast<float4*>(dyn);                 // 32 KB
    float*  stks = reinterpret_cast<float*>(dyn + SMEM_PTS_BYTES); // 24 KB

    __shared__ int sbstart[NB + 1];
    __shared__ float red[SCAN_THREADS];
    __shared__ float dd[CLOUDS];
    __shared__ int last;

    const int bx    = blockIdx.x;
    const int cloud = bx >> 4;
    const int chunk = bx & 15;
    const int tid   = threadIdx.x;
    const int wid   = tid >> 5;
    const int lane  = tid & 31;

    float* __restrict__ stk = stks + wid * (CAP * 32);

    const float4* __restrict__ gs = g_sorted + (size_t)cloud * N;
    for (int i = tid; i < N; i += SCAN_THREADS) spts[i] = gs[i];
    for (int i = tid; i < NB + 1; i += SCAN_THREADS) sbstart[i] = g_bstart[cloud][i];
    const float2 ci = g_cinfo[cloud];
    __syncthreads();

    const int qbase = chunk * SCAN_THREADS + wid * 32;
    const int myp   = qbase + lane;

    const float4 xi = spts[myp];
    const float ai = xi.w;
    const float mx = -2.0f * xi.x;
    const float my = -2.0f * xi.y;
    const float mz = -2.0f * xi.z;

    float a[KNN];
#pragma unroll
    for (int q = 0; q < KNN; ++q) a[q] = 3.4e38f;
    float t = 3.4e38f;

    // ---- seed: 3 batches (48 x-nearest candidates incl. self) ----
    int s0 = qbase - 16;
    if (s0 < 0) s0 = 0;
    if (s0 > N - 48) s0 = N - 48;
#pragma unroll
    for (int s = 0; s < 3; ++s) {
        float c[16];
#pragma unroll
        for (int q = 0; q < 16; ++q) {
            float4 sp = spts[s0 + 16 * s + q];
            float d = ai + sp.w;
            d = fmaf(mx, sp.x, d);
            d = fmaf(my, sp.y, d);
            d = fmaf(mz, sp.z, d);
            c[q] = d;
        }
        merge_batch(a, c, t);
    }

    // ---- exact conservative window from seeded t (warp-uniform) ----
    float r = sqrtf(t) * 1.0000002f;
    float xlo = xi.x - r;
    float xhi = xi.x + r;
#pragma unroll
    for (int off = 16; off >= 1; off >>= 1) {
        xlo = fminf(xlo, __shfl_xor_sync(0xffffffffu, xlo, off));
        xhi = fmaxf(xhi, __shfl_xor_sync(0xffffffffu, xhi, off));
    }
    int b_lo = (int)((xlo - ci.x) * ci.y); b_lo = max(0, min(NB - 1, b_lo));
    int b_hi = (int)((xhi - ci.x) * ci.y); b_hi = max(0, min(NB - 1, b_hi));
    const int w_lo = sbstart[b_lo];
    const int w_hi = sbstart[b_hi + 1];

    // ---- branchless filter scan (skips the 48 seed candidates) ----
    int cnt = 0;

    auto scan_range = [&](int beg, int end) {
        for (int j0 = beg; j0 < end; j0 += 16) {
            int stop = min(end, j0 + 16);
#pragma unroll 4
            for (int j = j0; j < stop; ++j) {
                float4 sp = spts[j];            // warp-broadcast LDS.128
                float d = ai + sp.w;
                d = fmaf(mx, sp.x, d);
                d = fmaf(my, sp.y, d);
                d = fmaf(mz, sp.z, d);
                stk[cnt * 32 + lane] = d;       // conflict-free STS (slack ok)
                cnt += (d < t) ? 1 : 0;         // predicated bump
            }
            if (__any_sync(0xffffffffu, cnt >= FLUSH_AT))
                flush_stk(stk, lane, cnt, a, t);  // rare; tightens t
        }
    };

    scan_range(w_lo, min(w_hi, s0));
    scan_range(max(w_lo, s0 + 48), w_hi);
    flush_stk(stk, lane, cnt, a, t);

    // ---- per-point mean of 16 nearest ----
    float s16 = 0.0f;
#pragma unroll
    for (int q = 0; q < KNN; ++q) s16 += a[q];
    red[tid] = s16 * (1.0f / KNN);
    __syncthreads();

    // ---- block reduction ----
#pragma unroll
    for (int s = SCAN_THREADS / 2; s > 0; s >>= 1) {
        if (tid < s) red[tid] += red[tid + s];
        __syncthreads();
    }
    if (tid == 0) g_partial[bx] = red[0];

    // ---- last-block finalize ----
    __threadfence();
    if (tid == 0) last = (atomicAdd(&g_count, 1) == SCAN_BLOCKS - 1);
    __syncthreads();
    if (last) {
        if (tid < CLOUDS) {
            float s = 0.0f;
#pragma unroll
            for (int c2 = 0; c2 < CHUNKS; ++c2)
                s += __ldcg(&g_partial[tid * CHUNKS + c2]);
            dd[tid] = s * (1.0f / N);
        }
        __syncthreads();
        if (tid == 0) {
            float loss = 0.0f;
#pragma unroll
            for (int b = 0; b < B; ++b) {
                float df = dd[b] - dd[B + b];
                loss += df * df;
            }
            out[0] = loss * (1.0f / B);
            g_count = 0;   // reset for next graph replay
        }
    }
}

extern "C" void kernel_launch(void* const* d_in, const int* in_sizes, int n_in,
                              void* d_out, int out_size) {
    const float* seed = (const float*)d_in[0];
    const float* gt_s = (const float*)d_in[1];
    float* out = (float*)d_out;

    static int attr_done = 0;
    if (!attr_done) {
        cudaFuncSetAttribute(scan_kernel,
                             cudaFuncAttributeMaxDynamicSharedMemorySize,
                             SMEM_DYN_BYTES);
        attr_done = 1;
    }

    bucket_kernel<<<CLOUDS, SORT_THREADS>>>(seed, gt_s);
    scan_kernel<<<SCAN_BLOCKS, SCAN_THREADS, SMEM_DYN_BYTES>>>(out);
}